// round 1
// baseline (speedup 1.0000x reference)
#include <cuda_runtime.h>

// ---------------------------------------------------------------------------
// 3-layer GraphSAGE (mean aggregation), fp32.
//   per layer: aggr = segment_mean(x[src] -> dst); out = aggr@W_l + b + x@W_r
//   relu after layers 0,1.
// N = 100000 nodes, E = 1600000 edges, dims 128 -> 256 -> 256 -> 256.
// ---------------------------------------------------------------------------

#define NN 100000
#define NE 1600000
#define CMAX 256

// Scratch (device globals: no allocation allowed in kernel_launch)
__device__ float g_agg[(size_t)NN * CMAX];   // aggregation accumulator
__device__ float g_h0 [(size_t)NN * CMAX];   // layer-0 output
__device__ float g_h1 [(size_t)NN * CMAX];   // layer-1 output
__device__ float g_deg[NN];
__device__ float g_invdeg[NN];

// ---------------------------------------------------------------------------
// small helper kernels
// ---------------------------------------------------------------------------
__global__ void k_zero_deg() {
    int i = blockIdx.x * blockDim.x + threadIdx.x;
    if (i < NN) g_deg[i] = 0.0f;
}

__global__ void k_deg(const int* __restrict__ dst) {
    int i = blockIdx.x * blockDim.x + threadIdx.x;
    if (i < NE) atomicAdd(&g_deg[dst[i]], 1.0f);
}

__global__ void k_invdeg() {
    int i = blockIdx.x * blockDim.x + threadIdx.x;
    if (i < NN) g_invdeg[i] = 1.0f / fmaxf(g_deg[i], 1.0f);
}

__global__ void k_zero_agg(int n4) {
    int i = blockIdx.x * blockDim.x + threadIdx.x;
    if (i < n4) reinterpret_cast<float4*>(g_agg)[i] = make_float4(0.f, 0.f, 0.f, 0.f);
}

// ---------------------------------------------------------------------------
// Edge scatter: agg[dst] += x[src], vectorized 16B atomic reductions.
// CVEC = channels/4 (32 for C=128, 64 for C=256). One thread = one float4.
// ---------------------------------------------------------------------------
__device__ __forceinline__ void red_add_f4(float* addr, float4 v) {
    asm volatile("red.global.add.v4.f32 [%0], {%1, %2, %3, %4};"
                 :: "l"(addr), "f"(v.x), "f"(v.y), "f"(v.z), "f"(v.w)
                 : "memory");
}

template <int CVEC, int LOG2V>
__global__ void k_scatter(const float* __restrict__ xext, int xsel,
                          const int* __restrict__ src,
                          const int* __restrict__ dst) {
    const float* x = (xsel == 0) ? xext : (xsel == 1 ? g_h0 : g_h1);
    long long i = (long long)blockIdx.x * blockDim.x + threadIdx.x;
    if (i >= (long long)NE * CVEC) return;
    int e = (int)(i >> LOG2V);
    int c = (int)(i & (CVEC - 1));
    int s = __ldg(&src[e]);
    int d = __ldg(&dst[e]);
    float4 v = reinterpret_cast<const float4*>(x)[(size_t)s * CVEC + c];
    red_add_f4(g_agg + ((size_t)d * CVEC + c) * 4, v);
}

// ---------------------------------------------------------------------------
// Fused dual-GEMM + bias + relu:
//   C = (g_agg * invdeg_row) @ B1  +  A2 @ B2  + bias      [N x 256]
// SIMT fp32 SGEMM, 128x128 block tile, BK=16, 256 threads, 8x8 per thread.
// ---------------------------------------------------------------------------
#define BM 128
#define BN 128
#define BK 16
#define PADM (BM + 4)

__global__ __launch_bounds__(256, 2)
void k_gemm(const float* __restrict__ A2ext, int a2sel,
            const float* __restrict__ B1,     // W_l [K,256]
            const float* __restrict__ B2,     // W_r [K,256]
            const float* __restrict__ bias,   // [256]
            float* __restrict__ Cext, int csel,
            int K, int relu) {
    __shared__ float As[BK][PADM];
    __shared__ float Bs[BK][BN];

    const float* A2 = (a2sel == 0) ? A2ext : (a2sel == 1 ? g_h0 : g_h1);
    float* C        = (csel == 0) ? Cext  : (csel == 1 ? g_h0 : g_h1);

    const int tid = threadIdx.x;
    const int bm  = blockIdx.x * BM;
    const int bn  = blockIdx.y * BN;

    const int rt = (tid >> 4) * 4;   // thread row base (plus +64 half)
    const int ct = (tid & 15) * 4;   // thread col base (plus +64 half)

    float acc[8][8];
#pragma unroll
    for (int i = 0; i < 8; i++)
#pragma unroll
        for (int j = 0; j < 8; j++) acc[i][j] = 0.0f;

#pragma unroll 1
    for (int part = 0; part < 2; ++part) {
        const float* A = (part == 0) ? g_agg : A2;
        const float* B = (part == 0) ? B1 : B2;
        const bool scale = (part == 0);

#pragma unroll 1
        for (int k0 = 0; k0 < K; k0 += BK) {
            __syncthreads();
            // load A tile (BM x BK), store transposed into As[k][m]
#pragma unroll
            for (int it = 0; it < 2; ++it) {
                int f  = tid + 256 * it;
                int r  = f >> 2;
                int kc = (f & 3) << 2;
                int row = bm + r;
                float4 v = make_float4(0.f, 0.f, 0.f, 0.f);
                if (row < NN) {
                    v = *reinterpret_cast<const float4*>(A + (size_t)row * K + k0 + kc);
                    if (scale) {
                        float s = g_invdeg[row];
                        v.x *= s; v.y *= s; v.z *= s; v.w *= s;
                    }
                }
                As[kc + 0][r] = v.x;
                As[kc + 1][r] = v.y;
                As[kc + 2][r] = v.z;
                As[kc + 3][r] = v.w;
            }
            // load B tile (BK x BN)
#pragma unroll
            for (int it = 0; it < 2; ++it) {
                int f = tid + 256 * it;
                int k = f >> 5;
                int c = (f & 31) << 2;
                *reinterpret_cast<float4*>(&Bs[k][c]) =
                    *reinterpret_cast<const float4*>(B + (size_t)(k0 + k) * 256 + bn + c);
            }
            __syncthreads();

#pragma unroll
            for (int k = 0; k < BK; ++k) {
                float a[8], b[8];
                *reinterpret_cast<float4*>(&a[0]) = *reinterpret_cast<const float4*>(&As[k][rt]);
                *reinterpret_cast<float4*>(&a[4]) = *reinterpret_cast<const float4*>(&As[k][rt + 64]);
                *reinterpret_cast<float4*>(&b[0]) = *reinterpret_cast<const float4*>(&Bs[k][ct]);
                *reinterpret_cast<float4*>(&b[4]) = *reinterpret_cast<const float4*>(&Bs[k][ct + 64]);
#pragma unroll
                for (int i = 0; i < 8; i++)
#pragma unroll
                    for (int j = 0; j < 8; j++) acc[i][j] += a[i] * b[j];
            }
        }
    }

    // epilogue: bias + relu + store
    float bl[8];
    *reinterpret_cast<float4*>(&bl[0]) = *reinterpret_cast<const float4*>(bias + bn + ct);
    *reinterpret_cast<float4*>(&bl[4]) = *reinterpret_cast<const float4*>(bias + bn + ct + 64);

#pragma unroll
    for (int i = 0; i < 8; i++) {
        int row = bm + rt + ((i < 4) ? i : (64 + i - 4));
        if (row >= NN) continue;
#pragma unroll
        for (int jj = 0; jj < 2; jj++) {
            float4 o;
            o.x = acc[i][jj * 4 + 0] + bl[jj * 4 + 0];
            o.y = acc[i][jj * 4 + 1] + bl[jj * 4 + 1];
            o.z = acc[i][jj * 4 + 2] + bl[jj * 4 + 2];
            o.w = acc[i][jj * 4 + 3] + bl[jj * 4 + 3];
            if (relu) {
                o.x = fmaxf(o.x, 0.f); o.y = fmaxf(o.y, 0.f);
                o.z = fmaxf(o.z, 0.f); o.w = fmaxf(o.w, 0.f);
            }
            *reinterpret_cast<float4*>(C + (size_t)row * 256 + bn + ct + jj * 64) = o;
        }
    }
}

// ---------------------------------------------------------------------------
// launch
// ---------------------------------------------------------------------------
extern "C" void kernel_launch(void* const* d_in, const int* in_sizes, int n_in,
                              void* d_out, int out_size) {
    const float* x    = (const float*)d_in[0];
    const float* W_l0 = (const float*)d_in[1];
    const float* b_l0 = (const float*)d_in[2];
    const float* W_r0 = (const float*)d_in[3];
    const float* W_l1 = (const float*)d_in[4];
    const float* b_l1 = (const float*)d_in[5];
    const float* W_r1 = (const float*)d_in[6];
    const float* W_l2 = (const float*)d_in[7];
    const float* b_l2 = (const float*)d_in[8];
    const float* W_r2 = (const float*)d_in[9];
    const int*   src  = (const int*)d_in[10];
    const int*   dst  = (const int*)d_in[11];
    float*       out  = (float*)d_out;

    const int T = 256;
    dim3 gemm_grid((NN + BM - 1) / BM, 256 / BN);

    // degree (float, to match reference semantics)
    k_zero_deg<<<(NN + T - 1) / T, T>>>();
    k_deg<<<(NE + T - 1) / T, T>>>(dst);
    k_invdeg<<<(NN + T - 1) / T, T>>>();

    // ---- layer 0 (C_in = 128) ----
    {
        int n4 = NN * 128 / 4;
        k_zero_agg<<<(n4 + T - 1) / T, T>>>(n4);
        long long nt = (long long)NE * 32;
        k_scatter<32, 5><<<(unsigned)((nt + T - 1) / T), T>>>(x, 0, src, dst);
        k_gemm<<<gemm_grid, T>>>(x, 0, W_l0, W_r0, b_l0, nullptr, 1, 128, 1);
    }
    // ---- layer 1 (C = 256) ----
    {
        int n4 = NN * 256 / 4;
        k_zero_agg<<<(n4 + T - 1) / T, T>>>(n4);
        long long nt = (long long)NE * 64;
        k_scatter<64, 6><<<(unsigned)((nt + T - 1) / T), T>>>(nullptr, 1, src, dst);
        k_gemm<<<gemm_grid, T>>>(nullptr, 1, W_l1, W_r1, b_l1, nullptr, 2, 256, 1);
    }
    // ---- layer 2 (C = 256, no relu, write d_out) ----
    {
        int n4 = NN * 256 / 4;
        k_zero_agg<<<(n4 + T - 1) / T, T>>>(n4);
        long long nt = (long long)NE * 64;
        k_scatter<64, 6><<<(unsigned)((nt + T - 1) / T), T>>>(nullptr, 2, src, dst);
        k_gemm<<<gemm_grid, T>>>(nullptr, 2, W_l2, W_r2, b_l2, out, 0, 256, 0);
    }
}

// round 2
// speedup vs baseline: 1.0906x; 1.0906x over previous
#include <cuda_runtime.h>

// ---------------------------------------------------------------------------
// 3-layer GraphSAGE (mean aggregation), fp32.
//   per layer: aggr = segment_mean(x[src] -> dst); out = aggr@W_l + b + x@W_r
//   relu after layers 0,1.
// N = 100000 nodes, E = 1600000 edges, dims 128 -> 256 -> 256 -> 256.
// GEMM inner loop uses packed fma.rn.f32x2 (2 FMA per issue slot).
// ---------------------------------------------------------------------------

#define NN 100000
#define NE 1600000
#define CMAX 256

typedef unsigned long long ull;

// Scratch (device globals: no allocation allowed in kernel_launch)
__device__ float g_agg[(size_t)NN * CMAX];   // aggregation accumulator
__device__ float g_h0 [(size_t)NN * CMAX];   // layer-0 output
__device__ float g_h1 [(size_t)NN * CMAX];   // layer-1 output
__device__ float g_deg[NN];
__device__ float g_invdeg[NN];

// ---------------------------------------------------------------------------
// small helper kernels
// ---------------------------------------------------------------------------
__global__ void k_zero_deg() {
    int i = blockIdx.x * blockDim.x + threadIdx.x;
    if (i < NN) g_deg[i] = 0.0f;
}

__global__ void k_deg(const int* __restrict__ dst) {
    int i = blockIdx.x * blockDim.x + threadIdx.x;
    if (i < NE) atomicAdd(&g_deg[dst[i]], 1.0f);
}

__global__ void k_invdeg() {
    int i = blockIdx.x * blockDim.x + threadIdx.x;
    if (i < NN) g_invdeg[i] = 1.0f / fmaxf(g_deg[i], 1.0f);
}

__global__ void k_zero_agg(int n4) {
    int i = blockIdx.x * blockDim.x + threadIdx.x;
    if (i < n4) reinterpret_cast<float4*>(g_agg)[i] = make_float4(0.f, 0.f, 0.f, 0.f);
}

// ---------------------------------------------------------------------------
// Edge scatter: agg[dst] += x[src], vectorized 16B atomic reductions.
// ---------------------------------------------------------------------------
__device__ __forceinline__ void red_add_f4(float* addr, float4 v) {
    asm volatile("red.global.add.v4.f32 [%0], {%1, %2, %3, %4};"
                 :: "l"(addr), "f"(v.x), "f"(v.y), "f"(v.z), "f"(v.w)
                 : "memory");
}

template <int CVEC, int LOG2V>
__global__ void k_scatter(const float* __restrict__ xext, int xsel,
                          const int* __restrict__ src,
                          const int* __restrict__ dst) {
    const float* x = (xsel == 0) ? xext : (xsel == 1 ? g_h0 : g_h1);
    long long i = (long long)blockIdx.x * blockDim.x + threadIdx.x;
    if (i >= (long long)NE * CVEC) return;
    int e = (int)(i >> LOG2V);
    int c = (int)(i & (CVEC - 1));
    int s = __ldg(&src[e]);
    int d = __ldg(&dst[e]);
    float4 v = reinterpret_cast<const float4*>(x)[(size_t)s * CVEC + c];
    red_add_f4(g_agg + ((size_t)d * CVEC + c) * 4, v);
}

// ---------------------------------------------------------------------------
// Fused dual-GEMM + bias + relu with packed f32x2 FMA:
//   C = (g_agg * invdeg_row) @ B1  +  A2 @ B2  + bias      [N x 256]
// 128x128 block tile, BK=16, 256 threads, 8x8 per thread (packed 8x4 pairs).
// ---------------------------------------------------------------------------
#define BM 128
#define BN 128
#define BK 16
#define PADM (BM + 4)

union F4U2 { float4 f; ull u[2]; };

__device__ __forceinline__ ull dup_f32(float a) {
    ull r;
    asm("mov.b64 %0, {%1, %1};" : "=l"(r) : "f"(a));
    return r;
}
__device__ __forceinline__ void ffma2(ull& d, ull a, ull b) {
    asm("fma.rn.f32x2 %0, %1, %2, %0;" : "+l"(d) : "l"(a), "l"(b));
}

__global__ __launch_bounds__(256, 2)
void k_gemm(const float* __restrict__ A2ext, int a2sel,
            const float* __restrict__ B1,     // W_l [K,256]
            const float* __restrict__ B2,     // W_r [K,256]
            const float* __restrict__ bias,   // [256]
            float* __restrict__ Cext, int csel,
            int K, int relu) {
    __shared__ float As[BK][PADM];
    __shared__ float Bs[BK][BN];

    const float* A2 = (a2sel == 0) ? A2ext : (a2sel == 1 ? g_h0 : g_h1);
    float* C        = (csel == 0) ? Cext  : (csel == 1 ? g_h0 : g_h1);

    const int tid = threadIdx.x;
    const int bm  = blockIdx.x * BM;
    const int bn  = blockIdx.y * BN;

    const int rt = (tid >> 4) * 4;   // thread row base (plus +64 half)
    const int ct = (tid & 15) * 4;   // thread col base (plus +64 half)

    // acc[i][j]: row i (0..7), packed column pair j (0..3)
    //   j=0 -> cols ct+0,ct+1; j=1 -> ct+2,ct+3; j=2 -> ct+64,ct+65; j=3 -> ct+66,ct+67
    ull acc[8][4];
#pragma unroll
    for (int i = 0; i < 8; i++)
#pragma unroll
        for (int j = 0; j < 4; j++) acc[i][j] = 0ull;

#pragma unroll 1
    for (int part = 0; part < 2; ++part) {
        const float* A = (part == 0) ? g_agg : A2;
        const float* B = (part == 0) ? B1 : B2;
        const bool scale = (part == 0);

#pragma unroll 1
        for (int k0 = 0; k0 < K; k0 += BK) {
            __syncthreads();
            // load A tile (BM x BK), store transposed into As[k][m]
#pragma unroll
            for (int it = 0; it < 2; ++it) {
                int f  = tid + 256 * it;
                int r  = f >> 2;
                int kc = (f & 3) << 2;
                int row = bm + r;
                float4 v = make_float4(0.f, 0.f, 0.f, 0.f);
                if (row < NN) {
                    v = *reinterpret_cast<const float4*>(A + (size_t)row * K + k0 + kc);
                    if (scale) {
                        float s = g_invdeg[row];
                        v.x *= s; v.y *= s; v.z *= s; v.w *= s;
                    }
                }
                As[kc + 0][r] = v.x;
                As[kc + 1][r] = v.y;
                As[kc + 2][r] = v.z;
                As[kc + 3][r] = v.w;
            }
            // load B tile (BK x BN)
#pragma unroll
            for (int it = 0; it < 2; ++it) {
                int f = tid + 256 * it;
                int k = f >> 5;
                int c = (f & 31) << 2;
                *reinterpret_cast<float4*>(&Bs[k][c]) =
                    *reinterpret_cast<const float4*>(B + (size_t)(k0 + k) * 256 + bn + c);
            }
            __syncthreads();

#pragma unroll
            for (int k = 0; k < BK; ++k) {
                float a[8];
                F4U2 b0, b1;
                *reinterpret_cast<float4*>(&a[0]) = *reinterpret_cast<const float4*>(&As[k][rt]);
                *reinterpret_cast<float4*>(&a[4]) = *reinterpret_cast<const float4*>(&As[k][rt + 64]);
                b0.f = *reinterpret_cast<const float4*>(&Bs[k][ct]);
                b1.f = *reinterpret_cast<const float4*>(&Bs[k][ct + 64]);
#pragma unroll
                for (int i = 0; i < 8; i++) {
                    ull a2 = dup_f32(a[i]);
                    ffma2(acc[i][0], a2, b0.u[0]);
                    ffma2(acc[i][1], a2, b0.u[1]);
                    ffma2(acc[i][2], a2, b1.u[0]);
                    ffma2(acc[i][3], a2, b1.u[1]);
                }
            }
        }
    }

    // epilogue: bias + relu + store
    float bl[8];
    *reinterpret_cast<float4*>(&bl[0]) = *reinterpret_cast<const float4*>(bias + bn + ct);
    *reinterpret_cast<float4*>(&bl[4]) = *reinterpret_cast<const float4*>(bias + bn + ct + 64);

#pragma unroll
    for (int i = 0; i < 8; i++) {
        int row = bm + rt + ((i < 4) ? i : (64 + i - 4));
        if (row >= NN) continue;
#pragma unroll
        for (int jj = 0; jj < 2; jj++) {
            float2 p0 = *reinterpret_cast<float2*>(&acc[i][jj * 2 + 0]);
            float2 p1 = *reinterpret_cast<float2*>(&acc[i][jj * 2 + 1]);
            float4 o;
            o.x = p0.x + bl[jj * 4 + 0];
            o.y = p0.y + bl[jj * 4 + 1];
            o.z = p1.x + bl[jj * 4 + 2];
            o.w = p1.y + bl[jj * 4 + 3];
            if (relu) {
                o.x = fmaxf(o.x, 0.f); o.y = fmaxf(o.y, 0.f);
                o.z = fmaxf(o.z, 0.f); o.w = fmaxf(o.w, 0.f);
            }
            *reinterpret_cast<float4*>(C + (size_t)row * 256 + bn + ct + jj * 64) = o;
        }
    }
}

// ---------------------------------------------------------------------------
// launch
// ---------------------------------------------------------------------------
extern "C" void kernel_launch(void* const* d_in, const int* in_sizes, int n_in,
                              void* d_out, int out_size) {
    const float* x    = (const float*)d_in[0];
    const float* W_l0 = (const float*)d_in[1];
    const float* b_l0 = (const float*)d_in[2];
    const float* W_r0 = (const float*)d_in[3];
    const float* W_l1 = (const float*)d_in[4];
    const float* b_l1 = (const float*)d_in[5];
    const float* W_r1 = (const float*)d_in[6];
    const float* W_l2 = (const float*)d_in[7];
    const float* b_l2 = (const float*)d_in[8];
    const float* W_r2 = (const float*)d_in[9];
    const int*   src  = (const int*)d_in[10];
    const int*   dst  = (const int*)d_in[11];
    float*       out  = (float*)d_out;

    const int T = 256;
    dim3 gemm_grid((NN + BM - 1) / BM, 256 / BN);

    // degree (float, to match reference semantics)
    k_zero_deg<<<(NN + T - 1) / T, T>>>();
    k_deg<<<(NE + T - 1) / T, T>>>(dst);
    k_invdeg<<<(NN + T - 1) / T, T>>>();

    // ---- layer 0 (C_in = 128) ----
    {
        int n4 = NN * 128 / 4;
        k_zero_agg<<<(n4 + T - 1) / T, T>>>(n4);
        long long nt = (long long)NE * 32;
        k_scatter<32, 5><<<(unsigned)((nt + T - 1) / T), T>>>(x, 0, src, dst);
        k_gemm<<<gemm_grid, T>>>(x, 0, W_l0, W_r0, b_l0, nullptr, 1, 128, 1);
    }
    // ---- layer 1 (C = 256) ----
    {
        int n4 = NN * 256 / 4;
        k_zero_agg<<<(n4 + T - 1) / T, T>>>(n4);
        long long nt = (long long)NE * 64;
        k_scatter<64, 6><<<(unsigned)((nt + T - 1) / T), T>>>(nullptr, 1, src, dst);
        k_gemm<<<gemm_grid, T>>>(nullptr, 1, W_l1, W_r1, b_l1, nullptr, 2, 256, 1);
    }
    // ---- layer 2 (C = 256, no relu, write d_out) ----
    {
        int n4 = NN * 256 / 4;
        k_zero_agg<<<(n4 + T - 1) / T, T>>>(n4);
        long long nt = (long long)NE * 64;
        k_scatter<64, 6><<<(unsigned)((nt + T - 1) / T), T>>>(nullptr, 2, src, dst);
        k_gemm<<<gemm_grid, T>>>(nullptr, 2, W_l2, W_r2, b_l2, out, 0, 256, 0);
    }
}

// round 3
// speedup vs baseline: 1.7733x; 1.6260x over previous
#include <cuda_runtime.h>

// ---------------------------------------------------------------------------
// 3-layer GraphSAGE (mean aggregation), fp32.
// Aggregation via CSR (dst-sorted) segment-sum gather — no float atomics.
// GEMM: fused dual-GEMM (aggr@W_l + x@W_r + b) with packed fma.rn.f32x2.
// N = 100000 nodes, E = 1600000 edges, dims 128 -> 256 -> 256 -> 256.
// ---------------------------------------------------------------------------

#define NN 100000
#define NE 1600000
#define CMAX 256

typedef unsigned long long ull;

// Scratch (device globals: no allocation allowed)
__device__ float g_agg[(size_t)NN * CMAX];   // normalized aggregation result
__device__ float g_h0 [(size_t)NN * CMAX];   // layer-0 output
__device__ float g_h1 [(size_t)NN * CMAX];   // layer-1 output

// CSR build
#define SCAN_B 512
#define NB1 ((NN + SCAN_B - 1) / SCAN_B)     // 196
__device__ int g_cnt[NN];                    // degree (segment length)
__device__ int g_pos[NN];                    // placement cursors
__device__ int g_rowptr[NN];                 // exclusive prefix (segment start)
__device__ int g_srcs[NE];                   // src node ids, grouped by dst
__device__ int g_scan[NN];                   // inclusive per-block scan
__device__ int g_part[NB1];                  // per-block totals
__device__ int g_partscan[NB1];              // scanned totals

// ---------------------------------------------------------------------------
// CSR build kernels
// ---------------------------------------------------------------------------
__global__ void k_zero_cnt() {
    int i = blockIdx.x * blockDim.x + threadIdx.x;
    if (i < NN) { g_cnt[i] = 0; g_pos[i] = 0; }
}

__global__ void k_hist(const int* __restrict__ dst) {
    int i = blockIdx.x * blockDim.x + threadIdx.x;
    if (i < NE) atomicAdd(&g_cnt[dst[i]], 1);
}

__global__ void k_scan1() {
    __shared__ int s[SCAN_B];
    int t = threadIdx.x;
    int idx = blockIdx.x * SCAN_B + t;
    int v = (idx < NN) ? g_cnt[idx] : 0;
    s[t] = v;
    __syncthreads();
#pragma unroll
    for (int off = 1; off < SCAN_B; off <<= 1) {
        int tmp = (t >= off) ? s[t - off] : 0;
        __syncthreads();
        s[t] += tmp;
        __syncthreads();
    }
    if (idx < NN) g_scan[idx] = s[t];
    if (t == SCAN_B - 1) g_part[blockIdx.x] = s[t];
}

__global__ void k_scan2() {
    __shared__ int s[256];
    int t = threadIdx.x;
    int v = (t < NB1) ? g_part[t] : 0;
    s[t] = v;
    __syncthreads();
#pragma unroll
    for (int off = 1; off < 256; off <<= 1) {
        int tmp = (t >= off) ? s[t - off] : 0;
        __syncthreads();
        s[t] += tmp;
        __syncthreads();
    }
    if (t < NB1) g_partscan[t] = s[t];
}

__global__ void k_scan3() {
    int idx = blockIdx.x * blockDim.x + threadIdx.x;
    if (idx < NN) {
        int b = idx / SCAN_B;
        int boff = (b > 0) ? g_partscan[b - 1] : 0;
        g_rowptr[idx] = g_scan[idx] - g_cnt[idx] + boff;   // exclusive
    }
}

__global__ void k_place(const int* __restrict__ src, const int* __restrict__ dst) {
    int i = blockIdx.x * blockDim.x + threadIdx.x;
    if (i < NE) {
        int d = dst[i];
        int pos = g_rowptr[d] + atomicAdd(&g_pos[d], 1);
        g_srcs[pos] = src[i];
    }
}

// ---------------------------------------------------------------------------
// Aggregation: segment-mean gather. One warp per (node, 128-ch chunk).
// Lane l accumulates float4 at channel offset chunk*32 + l. No atomics.
// ---------------------------------------------------------------------------
template <int CHUNKS>   // C = CHUNKS*128, CVEC4 = CHUNKS*32 float4 per row
__global__ void k_aggregate(const float* __restrict__ xext, int xsel) {
    const float* x = (xsel == 0) ? xext : (xsel == 1 ? g_h0 : g_h1);
    const int CV = CHUNKS * 32;

    int gw = (blockIdx.x * blockDim.x + threadIdx.x) >> 5;
    int lane = threadIdx.x & 31;
    int node = gw / CHUNKS;
    int chunk = gw - node * CHUNKS;
    if (node >= NN) return;

    int beg = g_rowptr[node];
    int len = g_cnt[node];
    int end = beg + len;
    size_t coff = (size_t)chunk * 32 + lane;

    const float4* xv = reinterpret_cast<const float4*>(x);
    float4 acc = make_float4(0.f, 0.f, 0.f, 0.f);

    int j = beg;
    for (; j + 4 <= end; j += 4) {
        int s0 = __ldg(&g_srcs[j + 0]);
        int s1 = __ldg(&g_srcs[j + 1]);
        int s2 = __ldg(&g_srcs[j + 2]);
        int s3 = __ldg(&g_srcs[j + 3]);
        float4 v0 = xv[(size_t)s0 * CV + coff];
        float4 v1 = xv[(size_t)s1 * CV + coff];
        float4 v2 = xv[(size_t)s2 * CV + coff];
        float4 v3 = xv[(size_t)s3 * CV + coff];
        acc.x += v0.x; acc.y += v0.y; acc.z += v0.z; acc.w += v0.w;
        acc.x += v1.x; acc.y += v1.y; acc.z += v1.z; acc.w += v1.w;
        acc.x += v2.x; acc.y += v2.y; acc.z += v2.z; acc.w += v2.w;
        acc.x += v3.x; acc.y += v3.y; acc.z += v3.z; acc.w += v3.w;
    }
    for (; j < end; ++j) {
        int s = __ldg(&g_srcs[j]);
        float4 v = xv[(size_t)s * CV + coff];
        acc.x += v.x; acc.y += v.y; acc.z += v.z; acc.w += v.w;
    }

    float inv = 1.0f / fmaxf((float)len, 1.0f);
    acc.x *= inv; acc.y *= inv; acc.z *= inv; acc.w *= inv;
    reinterpret_cast<float4*>(g_agg)[(size_t)node * CV + coff] = acc;
}

// ---------------------------------------------------------------------------
// Fused dual-GEMM + bias + relu with packed f32x2 FMA:
//   C = g_agg @ B1  +  A2 @ B2  + bias      [N x 256]
// 128x128 block tile, BK=16, 256 threads, 8x8 per thread (packed pairs).
// ---------------------------------------------------------------------------
#define BM 128
#define BN 128
#define BK 16
#define PADM (BM + 4)

union F4U2 { float4 f; ull u[2]; };

__device__ __forceinline__ ull dup_f32(float a) {
    ull r;
    asm("mov.b64 %0, {%1, %1};" : "=l"(r) : "f"(a));
    return r;
}
__device__ __forceinline__ void ffma2(ull& d, ull a, ull b) {
    asm("fma.rn.f32x2 %0, %1, %2, %0;" : "+l"(d) : "l"(a), "l"(b));
}

__global__ __launch_bounds__(256, 2)
void k_gemm(const float* __restrict__ A2ext, int a2sel,
            const float* __restrict__ B1,     // W_l [K,256]
            const float* __restrict__ B2,     // W_r [K,256]
            const float* __restrict__ bias,   // [256]
            float* __restrict__ Cext, int csel,
            int K, int relu) {
    __shared__ float As[BK][PADM];
    __shared__ float Bs[BK][BN];

    const float* A2 = (a2sel == 0) ? A2ext : (a2sel == 1 ? g_h0 : g_h1);
    float* C        = (csel == 0) ? Cext  : (csel == 1 ? g_h0 : g_h1);

    const int tid = threadIdx.x;
    const int bm  = blockIdx.x * BM;
    const int bn  = blockIdx.y * BN;

    const int rt = (tid >> 4) * 4;
    const int ct = (tid & 15) * 4;

    ull acc[8][4];
#pragma unroll
    for (int i = 0; i < 8; i++)
#pragma unroll
        for (int j = 0; j < 4; j++) acc[i][j] = 0ull;

#pragma unroll 1
    for (int part = 0; part < 2; ++part) {
        const float* A = (part == 0) ? g_agg : A2;
        const float* B = (part == 0) ? B1 : B2;

#pragma unroll 1
        for (int k0 = 0; k0 < K; k0 += BK) {
            __syncthreads();
#pragma unroll
            for (int it = 0; it < 2; ++it) {
                int f  = tid + 256 * it;
                int r  = f >> 2;
                int kc = (f & 3) << 2;
                int row = bm + r;
                float4 v = make_float4(0.f, 0.f, 0.f, 0.f);
                if (row < NN)
                    v = *reinterpret_cast<const float4*>(A + (size_t)row * K + k0 + kc);
                As[kc + 0][r] = v.x;
                As[kc + 1][r] = v.y;
                As[kc + 2][r] = v.z;
                As[kc + 3][r] = v.w;
            }
#pragma unroll
            for (int it = 0; it < 2; ++it) {
                int f = tid + 256 * it;
                int k = f >> 5;
                int c = (f & 31) << 2;
                *reinterpret_cast<float4*>(&Bs[k][c]) =
                    *reinterpret_cast<const float4*>(B + (size_t)(k0 + k) * 256 + bn + c);
            }
            __syncthreads();

#pragma unroll
            for (int k = 0; k < BK; ++k) {
                float a[8];
                F4U2 b0, b1;
                *reinterpret_cast<float4*>(&a[0]) = *reinterpret_cast<const float4*>(&As[k][rt]);
                *reinterpret_cast<float4*>(&a[4]) = *reinterpret_cast<const float4*>(&As[k][rt + 64]);
                b0.f = *reinterpret_cast<const float4*>(&Bs[k][ct]);
                b1.f = *reinterpret_cast<const float4*>(&Bs[k][ct + 64]);
#pragma unroll
                for (int i = 0; i < 8; i++) {
                    ull a2 = dup_f32(a[i]);
                    ffma2(acc[i][0], a2, b0.u[0]);
                    ffma2(acc[i][1], a2, b0.u[1]);
                    ffma2(acc[i][2], a2, b1.u[0]);
                    ffma2(acc[i][3], a2, b1.u[1]);
                }
            }
        }
    }

    float bl[8];
    *reinterpret_cast<float4*>(&bl[0]) = *reinterpret_cast<const float4*>(bias + bn + ct);
    *reinterpret_cast<float4*>(&bl[4]) = *reinterpret_cast<const float4*>(bias + bn + ct + 64);

#pragma unroll
    for (int i = 0; i < 8; i++) {
        int row = bm + rt + ((i < 4) ? i : (64 + i - 4));
        if (row >= NN) continue;
#pragma unroll
        for (int jj = 0; jj < 2; jj++) {
            float2 p0 = *reinterpret_cast<float2*>(&acc[i][jj * 2 + 0]);
            float2 p1 = *reinterpret_cast<float2*>(&acc[i][jj * 2 + 1]);
            float4 o;
            o.x = p0.x + bl[jj * 4 + 0];
            o.y = p0.y + bl[jj * 4 + 1];
            o.z = p1.x + bl[jj * 4 + 2];
            o.w = p1.y + bl[jj * 4 + 3];
            if (relu) {
                o.x = fmaxf(o.x, 0.f); o.y = fmaxf(o.y, 0.f);
                o.z = fmaxf(o.z, 0.f); o.w = fmaxf(o.w, 0.f);
            }
            *reinterpret_cast<float4*>(C + (size_t)row * 256 + bn + ct + jj * 64) = o;
        }
    }
}

// ---------------------------------------------------------------------------
// launch
// ---------------------------------------------------------------------------
extern "C" void kernel_launch(void* const* d_in, const int* in_sizes, int n_in,
                              void* d_out, int out_size) {
    const float* x    = (const float*)d_in[0];
    const float* W_l0 = (const float*)d_in[1];
    const float* b_l0 = (const float*)d_in[2];
    const float* W_r0 = (const float*)d_in[3];
    const float* W_l1 = (const float*)d_in[4];
    const float* b_l1 = (const float*)d_in[5];
    const float* W_r1 = (const float*)d_in[6];
    const float* W_l2 = (const float*)d_in[7];
    const float* b_l2 = (const float*)d_in[8];
    const float* W_r2 = (const float*)d_in[9];
    const int*   src  = (const int*)d_in[10];
    const int*   dst  = (const int*)d_in[11];
    float*       out  = (float*)d_out;

    const int T = 256;
    dim3 gemm_grid((NN + BM - 1) / BM, 256 / BN);

    // ---- CSR build (dst-sorted src list) ----
    k_zero_cnt<<<(NN + T - 1) / T, T>>>();
    k_hist<<<(NE + T - 1) / T, T>>>(dst);
    k_scan1<<<NB1, SCAN_B>>>();
    k_scan2<<<1, 256>>>();
    k_scan3<<<(NN + T - 1) / T, T>>>();
    k_place<<<(NE + T - 1) / T, T>>>(src, dst);

    // ---- layer 0 (C_in = 128) ----
    {
        int warps = NN * 1;
        k_aggregate<1><<<(warps * 32 + T - 1) / T, T>>>(x, 0);
        k_gemm<<<gemm_grid, T>>>(x, 0, W_l0, W_r0, b_l0, nullptr, 1, 128, 1);
    }
    // ---- layer 1 (C = 256) ----
    {
        int warps = NN * 2;
        k_aggregate<2><<<(warps * 32 + T - 1) / T, T>>>(nullptr, 1);
        k_gemm<<<gemm_grid, T>>>(nullptr, 1, W_l1, W_r1, b_l1, nullptr, 2, 256, 1);
    }
    // ---- layer 2 (C = 256, no relu, write d_out) ----
    {
        int warps = NN * 2;
        k_aggregate<2><<<(warps * 32 + T - 1) / T, T>>>(nullptr, 2);
        k_gemm<<<gemm_grid, T>>>(nullptr, 2, W_l2, W_r2, b_l2, out, 0, 256, 0);
    }
}

// round 5
// speedup vs baseline: 2.6486x; 1.4936x over previous
#include <cuda_runtime.h>
#include <cuda_bf16.h>
#include <cstdint>

// ---------------------------------------------------------------------------
// 3-layer GraphSAGE (mean aggregation), fp32.
//   aggregation: CSR (dst-sorted) segment-mean gather (no float atomics)
//   GEMM: warp-level mma.sync bf16 (m16n8k16), 3-product hi/lo split
//         C = aggr @ W_l + x @ W_r + b  [+relu]
// N = 100000, E = 1600000, dims 128 -> 256 -> 256 -> 256.
// ---------------------------------------------------------------------------

#define NN 100000
#define NE 1600000
#define CMAX 256

// ---------------- scratch (device globals; no allocation allowed) ----------
__device__ float g_agg[(size_t)NN * CMAX];
__device__ float g_h0 [(size_t)NN * CMAX];
__device__ float g_h1 [(size_t)NN * CMAX];

// transposed + bf16-split weights, [N=256, K] layout (K contiguous)
// offsets: l0:0(K=128) r0:32768  l1:65536 r1:131072 l2:196608 r2:262144
#define WBUF_TOTAL (2 * 128 * 256 + 4 * 256 * 256)
__device__ __nv_bfloat16 g_Wh[WBUF_TOTAL];
__device__ __nv_bfloat16 g_Wl[WBUF_TOTAL];

// CSR build
#define SCAN_B 512
#define NB1 ((NN + SCAN_B - 1) / SCAN_B)
__device__ int g_cnt[NN];
__device__ int g_pos[NN];
__device__ int g_rowptr[NN];
__device__ int g_srcs[NE];
__device__ int g_scan[NN];
__device__ int g_part[NB1];
__device__ int g_partscan[NB1];

// ---------------------------------------------------------------------------
// CSR build kernels
// ---------------------------------------------------------------------------
__global__ void k_zero_cnt() {
    int i = blockIdx.x * blockDim.x + threadIdx.x;
    if (i < NN) { g_cnt[i] = 0; g_pos[i] = 0; }
}
__global__ void k_hist(const int* __restrict__ dst) {
    int i = blockIdx.x * blockDim.x + threadIdx.x;
    if (i < NE) atomicAdd(&g_cnt[dst[i]], 1);
}
__global__ void k_scan1() {
    __shared__ int s[SCAN_B];
    int t = threadIdx.x;
    int idx = blockIdx.x * SCAN_B + t;
    int v = (idx < NN) ? g_cnt[idx] : 0;
    s[t] = v;
    __syncthreads();
#pragma unroll
    for (int off = 1; off < SCAN_B; off <<= 1) {
        int tmp = (t >= off) ? s[t - off] : 0;
        __syncthreads();
        s[t] += tmp;
        __syncthreads();
    }
    if (idx < NN) g_scan[idx] = s[t];
    if (t == SCAN_B - 1) g_part[blockIdx.x] = s[t];
}
__global__ void k_scan2() {
    __shared__ int s[256];
    int t = threadIdx.x;
    int v = (t < NB1) ? g_part[t] : 0;
    s[t] = v;
    __syncthreads();
#pragma unroll
    for (int off = 1; off < 256; off <<= 1) {
        int tmp = (t >= off) ? s[t - off] : 0;
        __syncthreads();
        s[t] += tmp;
        __syncthreads();
    }
    if (t < NB1) g_partscan[t] = s[t];
}
__global__ void k_scan3() {
    int idx = blockIdx.x * blockDim.x + threadIdx.x;
    if (idx < NN) {
        int b = idx / SCAN_B;
        int boff = (b > 0) ? g_partscan[b - 1] : 0;
        g_rowptr[idx] = g_scan[idx] - g_cnt[idx] + boff;
    }
}
__global__ void k_place(const int* __restrict__ src, const int* __restrict__ dst) {
    int i = blockIdx.x * blockDim.x + threadIdx.x;
    if (i < NE) {
        int d = dst[i];
        int pos = g_rowptr[d] + atomicAdd(&g_pos[d], 1);
        g_srcs[pos] = src[i];
    }
}

// ---------------------------------------------------------------------------
// weight prep: W[K,256] -> transposed [256,K], bf16 hi/lo split
// ---------------------------------------------------------------------------
__global__ void k_prep_w(const float* __restrict__ W, int K, int outoff) {
    int i = blockIdx.x * blockDim.x + threadIdx.x;
    if (i >= K * 256) return;
    int k = i >> 8, n = i & 255;
    float w = W[i];
    __nv_bfloat16 h = __float2bfloat16_rn(w);
    __nv_bfloat16 l = __float2bfloat16_rn(w - __bfloat162float(h));
    g_Wh[outoff + n * K + k] = h;
    g_Wl[outoff + n * K + k] = l;
}

// ---------------------------------------------------------------------------
// aggregation: segment-mean gather. one warp per (node, 128-ch chunk).
// ---------------------------------------------------------------------------
template <int CHUNKS>
__global__ void k_aggregate(const float* __restrict__ xext, int xsel) {
    const float* x = (xsel == 0) ? xext : (xsel == 1 ? g_h0 : g_h1);
    const int CV = CHUNKS * 32;
    int gw = (blockIdx.x * blockDim.x + threadIdx.x) >> 5;
    int lane = threadIdx.x & 31;
    int node = gw / CHUNKS;
    int chunk = gw - node * CHUNKS;
    if (node >= NN) return;

    int beg = g_rowptr[node];
    int len = g_cnt[node];
    int end = beg + len;
    size_t coff = (size_t)chunk * 32 + lane;
    const float4* xv = reinterpret_cast<const float4*>(x);
    float4 acc = make_float4(0.f, 0.f, 0.f, 0.f);

    int j = beg;
    for (; j + 4 <= end; j += 4) {
        int s0 = __ldg(&g_srcs[j + 0]);
        int s1 = __ldg(&g_srcs[j + 1]);
        int s2 = __ldg(&g_srcs[j + 2]);
        int s3 = __ldg(&g_srcs[j + 3]);
        float4 v0 = xv[(size_t)s0 * CV + coff];
        float4 v1 = xv[(size_t)s1 * CV + coff];
        float4 v2 = xv[(size_t)s2 * CV + coff];
        float4 v3 = xv[(size_t)s3 * CV + coff];
        acc.x += v0.x; acc.y += v0.y; acc.z += v0.z; acc.w += v0.w;
        acc.x += v1.x; acc.y += v1.y; acc.z += v1.z; acc.w += v1.w;
        acc.x += v2.x; acc.y += v2.y; acc.z += v2.z; acc.w += v2.w;
        acc.x += v3.x; acc.y += v3.y; acc.z += v3.z; acc.w += v3.w;
    }
    for (; j < end; ++j) {
        int s = __ldg(&g_srcs[j]);
        float4 v = xv[(size_t)s * CV + coff];
        acc.x += v.x; acc.y += v.y; acc.z += v.z; acc.w += v.w;
    }
    float inv = 1.0f / fmaxf((float)len, 1.0f);
    acc.x *= inv; acc.y *= inv; acc.z *= inv; acc.w *= inv;
    reinterpret_cast<float4*>(g_agg)[(size_t)node * CV + coff] = acc;
}

// ---------------------------------------------------------------------------
// mma.sync bf16 dual-GEMM
//   CTA tile 128(M) x 128(N), BK=32, 8 warps each 32x64.
//   3 products per tile-pair: Ah*Bh + Al*Bh + Ah*Bl (fp32 accum).
// ---------------------------------------------------------------------------
#define BM 128
#define BN 128
#define SSTRIDE 40   // bf16 elements per smem row (32 data + 8 pad)

__device__ __forceinline__ void mma_bf16(float* c, const uint32_t* a, const uint32_t* b) {
    asm volatile(
        "mma.sync.aligned.m16n8k16.row.col.f32.bf16.bf16.f32 "
        "{%0,%1,%2,%3}, {%4,%5,%6,%7}, {%8,%9}, {%0,%1,%2,%3};"
        : "+f"(c[0]), "+f"(c[1]), "+f"(c[2]), "+f"(c[3])
        : "r"(a[0]), "r"(a[1]), "r"(a[2]), "r"(a[3]), "r"(b[0]), "r"(b[1]));
}

__device__ __forceinline__ uint32_t pack_bf16x2(__nv_bfloat16 a, __nv_bfloat16 b) {
    __nv_bfloat162 p = __halves2bfloat162(a, b);
    return *reinterpret_cast<uint32_t*>(&p);
}

__global__ __launch_bounds__(256, 2)
void k_gemm_mma(const float* __restrict__ A2ext, int a2sel,
                int woff_l, int woff_r,
                const float* __restrict__ bias,
                float* __restrict__ Cext, int csel,
                int K, int relu) {
    __shared__ __align__(16) __nv_bfloat16 sAh[BM * SSTRIDE];
    __shared__ __align__(16) __nv_bfloat16 sAl[BM * SSTRIDE];
    __shared__ __align__(16) __nv_bfloat16 sBh[BN * SSTRIDE];
    __shared__ __align__(16) __nv_bfloat16 sBl[BN * SSTRIDE];

    const float* A2 = (a2sel == 0) ? A2ext : (a2sel == 1 ? g_h0 : g_h1);
    float* C        = (csel == 0) ? Cext  : (csel == 1 ? g_h0 : g_h1);

    const int tid  = threadIdx.x;
    const int wid  = tid >> 5;
    const int lane = tid & 31;
    const int wm   = wid & 3;    // 4 warps along M -> 32 rows each
    const int wn   = wid >> 2;   // 2 warps along N -> 64 cols each
    const int bm   = blockIdx.x * BM;
    const int bn   = blockIdx.y * BN;

    const int r4 = lane >> 2;          // 0..7
    const int c2 = (lane & 3) * 2;     // 0,2,4,6

    float acc[2][8][4];
#pragma unroll
    for (int mt = 0; mt < 2; mt++)
#pragma unroll
        for (int nt = 0; nt < 8; nt++)
#pragma unroll
            for (int q = 0; q < 4; q++) acc[mt][nt][q] = 0.0f;

#pragma unroll 1
    for (int part = 0; part < 2; ++part) {
        const float* Ac = (part == 0) ? g_agg : A2;
        const __nv_bfloat16* Bh = g_Wh + (part == 0 ? woff_l : woff_r);
        const __nv_bfloat16* Bl = g_Wl + (part == 0 ? woff_l : woff_r);

#pragma unroll 1
        for (int k0 = 0; k0 < K; k0 += 32) {
            __syncthreads();
            // ---- stage A: 128 x 32 fp32 -> split bf16 hi/lo ----
#pragma unroll
            for (int i = 0; i < 4; ++i) {
                int f   = tid + 256 * i;
                int row = f >> 3;
                int c4  = f & 7;
                int rg  = bm + row;
                float4 v = make_float4(0.f, 0.f, 0.f, 0.f);
                if (rg < NN)
                    v = *reinterpret_cast<const float4*>(Ac + (size_t)rg * K + k0 + c4 * 4);
                __nv_bfloat16 hx = __float2bfloat16_rn(v.x);
                __nv_bfloat16 hy = __float2bfloat16_rn(v.y);
                __nv_bfloat16 hz = __float2bfloat16_rn(v.z);
                __nv_bfloat16 hw = __float2bfloat16_rn(v.w);
                __nv_bfloat16 lx = __float2bfloat16_rn(v.x - __bfloat162float(hx));
                __nv_bfloat16 ly = __float2bfloat16_rn(v.y - __bfloat162float(hy));
                __nv_bfloat16 lz = __float2bfloat16_rn(v.z - __bfloat162float(hz));
                __nv_bfloat16 lw = __float2bfloat16_rn(v.w - __bfloat162float(hw));
                uint2 ph = make_uint2(pack_bf16x2(hx, hy), pack_bf16x2(hz, hw));
                uint2 pl = make_uint2(pack_bf16x2(lx, ly), pack_bf16x2(lz, lw));
                *reinterpret_cast<uint2*>(&sAh[row * SSTRIDE + c4 * 4]) = ph;
                *reinterpret_cast<uint2*>(&sAl[row * SSTRIDE + c4 * 4]) = pl;
            }
            // ---- stage B: 128 x 32 bf16 (pre-split) ----
#pragma unroll
            for (int i = 0; i < 2; ++i) {
                int f = tid + 256 * i;
                int n = f >> 2;
                int q = f & 3;
                const __nv_bfloat16* ph = Bh + (size_t)(bn + n) * K + k0 + q * 8;
                const __nv_bfloat16* pl = Bl + (size_t)(bn + n) * K + k0 + q * 8;
                *reinterpret_cast<uint4*>(&sBh[n * SSTRIDE + q * 8]) =
                    *reinterpret_cast<const uint4*>(ph);
                *reinterpret_cast<uint4*>(&sBl[n * SSTRIDE + q * 8]) =
                    *reinterpret_cast<const uint4*>(pl);
            }
            __syncthreads();

            // ---- compute: 2 k-steps of 16 ----
#pragma unroll
            for (int kk = 0; kk < 32; kk += 16) {
                uint32_t ah[2][4], al[2][4];
#pragma unroll
                for (int mt = 0; mt < 2; ++mt) {
                    int rbase = (wm * 32 + mt * 16 + r4) * SSTRIDE + kk + c2;
                    ah[mt][0] = *reinterpret_cast<const uint32_t*>(&sAh[rbase]);
                    ah[mt][1] = *reinterpret_cast<const uint32_t*>(&sAh[rbase + 8 * SSTRIDE]);
                    ah[mt][2] = *reinterpret_cast<const uint32_t*>(&sAh[rbase + 8]);
                    ah[mt][3] = *reinterpret_cast<const uint32_t*>(&sAh[rbase + 8 * SSTRIDE + 8]);
                    al[mt][0] = *reinterpret_cast<const uint32_t*>(&sAl[rbase]);
                    al[mt][1] = *reinterpret_cast<const uint32_t*>(&sAl[rbase + 8 * SSTRIDE]);
                    al[mt][2] = *reinterpret_cast<const uint32_t*>(&sAl[rbase + 8]);
                    al[mt][3] = *reinterpret_cast<const uint32_t*>(&sAl[rbase + 8 * SSTRIDE + 8]);
                }
#pragma unroll
                for (int nt = 0; nt < 8; ++nt) {
                    int nbase = (wn * 64 + nt * 8 + r4) * SSTRIDE + kk + c2;
                    uint32_t bh[2], bl[2];
                    bh[0] = *reinterpret_cast<const uint32_t*>(&sBh[nbase]);
                    bh[1] = *reinterpret_cast<const uint32_t*>(&sBh[nbase + 8]);
                    bl[0] = *reinterpret_cast<const uint32_t*>(&sBl[nbase]);
                    bl[1] = *reinterpret_cast<const uint32_t*>(&sBl[nbase + 8]);
#pragma unroll
                    for (int mt = 0; mt < 2; ++mt) {
                        mma_bf16(acc[mt][nt], ah[mt], bh);
                        mma_bf16(acc[mt][nt], al[mt], bh);
                        mma_bf16(acc[mt][nt], ah[mt], bl);
                    }
                }
            }
        }
    }

    // ---- epilogue: bias + relu + store ----
#pragma unroll
    for (int nt = 0; nt < 8; ++nt) {
        int col = bn + wn * 64 + nt * 8 + c2;
        float2 bv = *reinterpret_cast<const float2*>(bias + col);
#pragma unroll
        for (int mt = 0; mt < 2; ++mt) {
            int row0 = bm + wm * 32 + mt * 16 + r4;
            float2 o0, o1;
            o0.x = acc[mt][nt][0] + bv.x;
            o0.y = acc[mt][nt][1] + bv.y;
            o1.x = acc[mt][nt][2] + bv.x;
            o1.y = acc[mt][nt][3] + bv.y;
            if (relu) {
                o0.x = fmaxf(o0.x, 0.f); o0.y = fmaxf(o0.y, 0.f);
                o1.x = fmaxf(o1.x, 0.f); o1.y = fmaxf(o1.y, 0.f);
            }
            if (row0 < NN)
                *reinterpret_cast<float2*>(C + (size_t)row0 * 256 + col) = o0;
            if (row0 + 8 < NN)
                *reinterpret_cast<float2*>(C + (size_t)(row0 + 8) * 256 + col) = o1;
        }
    }
}

// ---------------------------------------------------------------------------
// launch
// ---------------------------------------------------------------------------
extern "C" void kernel_launch(void* const* d_in, const int* in_sizes, int n_in,
                              void* d_out, int out_size) {
    const float* x    = (const float*)d_in[0];
    const float* W_l0 = (const float*)d_in[1];
    const float* b_l0 = (const float*)d_in[2];
    const float* W_r0 = (const float*)d_in[3];
    const float* W_l1 = (const float*)d_in[4];
    const float* b_l1 = (const float*)d_in[5];
    const float* W_r1 = (const float*)d_in[6];
    const float* W_l2 = (const float*)d_in[7];
    const float* b_l2 = (const float*)d_in[8];
    const float* W_r2 = (const float*)d_in[9];
    const int*   src  = (const int*)d_in[10];
    const int*   dst  = (const int*)d_in[11];
    float*       out  = (float*)d_out;

    const int T = 256;
    dim3 gemm_grid((NN + BM - 1) / BM, 256 / BN);

    // ---- CSR build ----
    k_zero_cnt<<<(NN + T - 1) / T, T>>>();
    k_hist<<<(NE + T - 1) / T, T>>>(dst);
    k_scan1<<<NB1, SCAN_B>>>();
    k_scan2<<<1, 256>>>();
    k_scan3<<<(NN + T - 1) / T, T>>>();
    k_place<<<(NE + T - 1) / T, T>>>(src, dst);

    // ---- weight prep (transpose + bf16 split) ----
    k_prep_w<<<(128 * 256 + T - 1) / T, T>>>(W_l0, 128, 0);
    k_prep_w<<<(128 * 256 + T - 1) / T, T>>>(W_r0, 128, 32768);
    k_prep_w<<<(256 * 256 + T - 1) / T, T>>>(W_l1, 256, 65536);
    k_prep_w<<<(256 * 256 + T - 1) / T, T>>>(W_r1, 256, 131072);
    k_prep_w<<<(256 * 256 + T - 1) / T, T>>>(W_l2, 256, 196608);
    k_prep_w<<<(256 * 256 + T - 1) / T, T>>>(W_r2, 256, 262144);

    // ---- layer 0 (K = 128) ----
    k_aggregate<1><<<(NN * 1 * 32 + T - 1) / T, T>>>(x, 0);
    k_gemm_mma<<<gemm_grid, T>>>(x, 0, 0, 32768, b_l0, nullptr, 1, 128, 1);

    // ---- layer 1 (K = 256) ----
    k_aggregate<2><<<(NN * 2 * 32 + T - 1) / T, T>>>(nullptr, 1);
    k_gemm_mma<<<gemm_grid, T>>>(nullptr, 1, 65536, 131072, b_l1, nullptr, 2, 256, 1);

    // ---- layer 2 (K = 256, no relu, write d_out) ----
    k_aggregate<2><<<(NN * 2 * 32 + T - 1) / T, T>>>(nullptr, 2);
    k_gemm_mma<<<gemm_grid, T>>>(nullptr, 2, 196608, 262144, b_l2, out, 0, 256, 0);
}

// round 6
// speedup vs baseline: 2.8956x; 1.0933x over previous
#include <cuda_runtime.h>
#include <cuda_bf16.h>
#include <cstdint>

// ---------------------------------------------------------------------------
// 3-layer GraphSAGE (mean aggregation), fp32-grade via bf16 hi/lo pairs.
//   activations stored packed: u32 = (bf16_hi << 16) | bf16_lo, value = hi+lo
//   aggregation: CSR segment-mean gather (no float atomics)
//   GEMM: mma.sync m16n8k16 bf16, 3 products (AhBh + AlBh + AhBl),
//         cp.async double-buffered pipeline, PRMT hi/lo extraction.
// N = 100000, E = 1600000, dims 128 -> 256 -> 256 -> 256.
// ---------------------------------------------------------------------------

#define NN 100000
#define NE 1600000
#define CMAX 256

// ---------------- packed activation buffers --------------------------------
__device__ uint32_t g_xp  [(size_t)NN * 128];
__device__ uint32_t g_aggp[(size_t)NN * CMAX];
__device__ uint32_t g_h0p [(size_t)NN * CMAX];
__device__ uint32_t g_h1p [(size_t)NN * CMAX];

// packed transposed weights [N=256, K] (K contiguous)
// offsets: l0:0(K=128) r0:32768  l1:65536 r1:131072 l2:196608 r2:262144
#define WBUF_TOTAL (2 * 128 * 256 + 4 * 256 * 256)
__device__ uint32_t g_Wp[WBUF_TOTAL];

// CSR build
#define SCAN_B 512
#define NB1 ((NN + SCAN_B - 1) / SCAN_B)
__device__ int g_cnt[NN];
__device__ int g_pos[NN];
__device__ int g_rowptr[NN];
__device__ int g_srcs[NE];
__device__ int g_scan[NN];
__device__ int g_part[NB1];
__device__ int g_partscan[NB1];

// ---------------------------------------------------------------------------
// helpers
// ---------------------------------------------------------------------------
__device__ __forceinline__ uint32_t pack_split(float v) {
    __nv_bfloat16 h = __float2bfloat16_rn(v);
    float r = v - __bfloat162float(h);
    __nv_bfloat16 l = __float2bfloat16_rn(r);
    return ((uint32_t)__bfloat16_as_ushort(h) << 16) | (uint32_t)__bfloat16_as_ushort(l);
}
__device__ __forceinline__ float unpack_val(uint32_t p) {
    return __uint_as_float(p & 0xFFFF0000u) + __uint_as_float(p << 16);
}
__device__ __forceinline__ void cpa16(uint32_t saddr, const void* g, int sz) {
    asm volatile("cp.async.ca.shared.global [%0], [%1], 16, %2;"
                 :: "r"(saddr), "l"(g), "r"(sz) : "memory");
}
__device__ __forceinline__ uint32_t smem_u32p(const void* p) {
    uint32_t a;
    asm("{ .reg .u64 t; cvta.to.shared.u64 t, %1; cvt.u32.u64 %0, t; }" : "=r"(a) : "l"(p));
    return a;
}
__device__ __forceinline__ void mma_bf16(float* c, const uint32_t* a, const uint32_t* b) {
    asm volatile(
        "mma.sync.aligned.m16n8k16.row.col.f32.bf16.bf16.f32 "
        "{%0,%1,%2,%3}, {%4,%5,%6,%7}, {%8,%9}, {%0,%1,%2,%3};"
        : "+f"(c[0]), "+f"(c[1]), "+f"(c[2]), "+f"(c[3])
        : "r"(a[0]), "r"(a[1]), "r"(a[2]), "r"(a[3]), "r"(b[0]), "r"(b[1]));
}

// ---------------------------------------------------------------------------
// CSR build kernels
// ---------------------------------------------------------------------------
__global__ void k_zero_cnt() {
    int i = blockIdx.x * blockDim.x + threadIdx.x;
    if (i < NN) { g_cnt[i] = 0; g_pos[i] = 0; }
}
__global__ void k_hist(const int* __restrict__ dst) {
    int i = blockIdx.x * blockDim.x + threadIdx.x;
    if (i < NE) atomicAdd(&g_cnt[dst[i]], 1);
}
__global__ void k_scan1() {
    __shared__ int s[SCAN_B];
    int t = threadIdx.x;
    int idx = blockIdx.x * SCAN_B + t;
    int v = (idx < NN) ? g_cnt[idx] : 0;
    s[t] = v;
    __syncthreads();
#pragma unroll
    for (int off = 1; off < SCAN_B; off <<= 1) {
        int tmp = (t >= off) ? s[t - off] : 0;
        __syncthreads();
        s[t] += tmp;
        __syncthreads();
    }
    if (idx < NN) g_scan[idx] = s[t];
    if (t == SCAN_B - 1) g_part[blockIdx.x] = s[t];
}
__global__ void k_scan2() {
    __shared__ int s[256];
    int t = threadIdx.x;
    int v = (t < NB1) ? g_part[t] : 0;
    s[t] = v;
    __syncthreads();
#pragma unroll
    for (int off = 1; off < 256; off <<= 1) {
        int tmp = (t >= off) ? s[t - off] : 0;
        __syncthreads();
        s[t] += tmp;
        __syncthreads();
    }
    if (t < NB1) g_partscan[t] = s[t];
}
__global__ void k_scan3() {
    int idx = blockIdx.x * blockDim.x + threadIdx.x;
    if (idx < NN) {
        int b = idx / SCAN_B;
        int boff = (b > 0) ? g_partscan[b - 1] : 0;
        g_rowptr[idx] = g_scan[idx] - g_cnt[idx] + boff;
    }
}
__global__ void k_place(const int* __restrict__ src, const int* __restrict__ dst) {
    int i = blockIdx.x * blockDim.x + threadIdx.x;
    if (i < NE) {
        int d = dst[i];
        int pos = g_rowptr[d] + atomicAdd(&g_pos[d], 1);
        g_srcs[pos] = src[i];
    }
}

// ---------------------------------------------------------------------------
// prep: pack x; pack+transpose weights
// ---------------------------------------------------------------------------
__global__ void k_prep_x(const float* __restrict__ x) {
    int i = blockIdx.x * blockDim.x + threadIdx.x;
    if (i < NN * 128) g_xp[i] = pack_split(x[i]);
}
__global__ void k_prep_w(const float* __restrict__ W, int K, int outoff) {
    int i = blockIdx.x * blockDim.x + threadIdx.x;
    if (i >= K * 256) return;
    int k = i >> 8, n = i & 255;
    g_Wp[outoff + n * K + k] = pack_split(W[i]);
}

// ---------------------------------------------------------------------------
// aggregation: segment-mean gather over packed values. one warp per
// (node, 128-ch chunk); lanes hold 4 channels each (uint4 of packed u32).
// ---------------------------------------------------------------------------
__device__ __forceinline__ void acc_packed(float4& a, uint4 v) {
    a.x += unpack_val(v.x);
    a.y += unpack_val(v.y);
    a.z += unpack_val(v.z);
    a.w += unpack_val(v.w);
}

template <int CHUNKS>
__global__ void k_aggregate(int xsel) {
    const uint32_t* x = (xsel == 0) ? g_xp : (xsel == 1 ? g_h0p : g_h1p);
    const int CV = CHUNKS * 32;   // uint4 per row
    int gw = (blockIdx.x * blockDim.x + threadIdx.x) >> 5;
    int lane = threadIdx.x & 31;
    int node = gw / CHUNKS;
    int chunk = gw - node * CHUNKS;
    if (node >= NN) return;

    int beg = g_rowptr[node];
    int len = g_cnt[node];
    int end = beg + len;
    size_t coff = (size_t)chunk * 32 + lane;
    const uint4* xv = reinterpret_cast<const uint4*>(x);
    float4 acc = make_float4(0.f, 0.f, 0.f, 0.f);

    int j = beg;
    for (; j + 4 <= end; j += 4) {
        int s0 = __ldg(&g_srcs[j + 0]);
        int s1 = __ldg(&g_srcs[j + 1]);
        int s2 = __ldg(&g_srcs[j + 2]);
        int s3 = __ldg(&g_srcs[j + 3]);
        uint4 v0 = xv[(size_t)s0 * CV + coff];
        uint4 v1 = xv[(size_t)s1 * CV + coff];
        uint4 v2 = xv[(size_t)s2 * CV + coff];
        uint4 v3 = xv[(size_t)s3 * CV + coff];
        acc_packed(acc, v0);
        acc_packed(acc, v1);
        acc_packed(acc, v2);
        acc_packed(acc, v3);
    }
    for (; j < end; ++j) {
        int s = __ldg(&g_srcs[j]);
        acc_packed(acc, xv[(size_t)s * CV + coff]);
    }
    float inv = 1.0f / fmaxf((float)len, 1.0f);
    uint4 o;
    o.x = pack_split(acc.x * inv);
    o.y = pack_split(acc.y * inv);
    o.z = pack_split(acc.z * inv);
    o.w = pack_split(acc.w * inv);
    reinterpret_cast<uint4*>(g_aggp)[(size_t)node * CV + coff] = o;
}

// ---------------------------------------------------------------------------
// GEMM: C[128,256-tilewise] = agg@W_l + A2@W_r + bias (+relu)
//   packed smem, cp.async 2-stage pipeline, PRMT hi/lo extraction at
//   fragment-load time, 3 mma products per tile.
// ---------------------------------------------------------------------------
#define BM 128
#define BN 128
#define S40 40                      // u32 stride per smem row (32 data + 8 pad)
#define ASZ (128 * S40)             // 5120 u32 per stage array
#define STGU (2 * ASZ)              // A + B per stage (u32)
#define SMEM_BYTES (2 * STGU * 4)   // 81920

__global__ __launch_bounds__(256, 2)
void k_gemm_mma(int a2sel, int woff_l, int woff_r,
                const float* __restrict__ bias,
                float* __restrict__ Cext, int csel,
                int K, int relu) {
    extern __shared__ uint32_t smem[];
    const uint32_t sb = smem_u32p(smem);

    const uint32_t* A2 = (a2sel == 0) ? g_xp : (a2sel == 1 ? g_h0p : g_h1p);
    const int tid  = threadIdx.x;
    const int wid  = tid >> 5;
    const int lane = tid & 31;
    const int wm   = wid & 3;
    const int wn   = wid >> 2;
    const int bm   = blockIdx.x * BM;
    const int bn   = blockIdx.y * BN;
    const int r4   = lane >> 2;
    const int c2   = (lane & 3) * 2;

    const int KCH = K / 32;
    const int NCH = 2 * KCH;

    float acc[2][8][4];
#pragma unroll
    for (int mt = 0; mt < 2; mt++)
#pragma unroll
        for (int nt = 0; nt < 8; nt++)
#pragma unroll
            for (int q = 0; q < 4; q++) acc[mt][nt][q] = 0.0f;

    // ---- async stage issue ----
    auto issue = [&](int c) {
        int part = (c >= KCH) ? 1 : 0;
        int k0 = (c - part * KCH) * 32;
        const uint32_t* Abase = part ? A2 : g_aggp;
        int woff = part ? woff_r : woff_l;
        int buf = c & 1;
        uint32_t sA = sb + (buf * STGU) * 4;
        uint32_t sB = sA + ASZ * 4;
#pragma unroll
        for (int i = 0; i < 4; ++i) {
            int f = tid + 256 * i;
            int row = f >> 3, c4 = f & 7;
            int rg = bm + row;
            const uint32_t* src = Abase + (size_t)rg * K + k0 + c4 * 4;
            cpa16(sA + (row * S40 + c4 * 4) * 4, src, (rg < NN) ? 16 : 0);
        }
#pragma unroll
        for (int i = 0; i < 4; ++i) {
            int f = tid + 256 * i;
            int n = f >> 3, c4 = f & 7;
            const uint32_t* src = g_Wp + woff + (size_t)(bn + n) * K + k0 + c4 * 4;
            cpa16(sB + (n * S40 + c4 * 4) * 4, src, 16);
        }
        asm volatile("cp.async.commit_group;" ::: "memory");
    };

    issue(0);
    if (NCH > 1) issue(1);

#pragma unroll 1
    for (int c = 0; c < NCH; ++c) {
        if (c + 1 < NCH)
            asm volatile("cp.async.wait_group 1;" ::: "memory");
        else
            asm volatile("cp.async.wait_group 0;" ::: "memory");
        __syncthreads();

        const uint32_t* sA = smem + (c & 1) * STGU;
        const uint32_t* sB = sA + ASZ;

#pragma unroll
        for (int kk = 0; kk < 32; kk += 16) {
            uint32_t ah[2][4], al[2][4];
#pragma unroll
            for (int mt = 0; mt < 2; ++mt) {
                int rb = (wm * 32 + mt * 16 + r4) * S40 + kk + c2;
                uint2 q0 = *reinterpret_cast<const uint2*>(&sA[rb]);
                uint2 q1 = *reinterpret_cast<const uint2*>(&sA[rb + 8 * S40]);
                uint2 q2 = *reinterpret_cast<const uint2*>(&sA[rb + 8]);
                uint2 q3 = *reinterpret_cast<const uint2*>(&sA[rb + 8 * S40 + 8]);
                ah[mt][0] = __byte_perm(q0.x, q0.y, 0x7632);
                al[mt][0] = __byte_perm(q0.x, q0.y, 0x5410);
                ah[mt][1] = __byte_perm(q1.x, q1.y, 0x7632);
                al[mt][1] = __byte_perm(q1.x, q1.y, 0x5410);
                ah[mt][2] = __byte_perm(q2.x, q2.y, 0x7632);
                al[mt][2] = __byte_perm(q2.x, q2.y, 0x5410);
                ah[mt][3] = __byte_perm(q3.x, q3.y, 0x7632);
                al[mt][3] = __byte_perm(q3.x, q3.y, 0x5410);
            }
#pragma unroll
            for (int nt = 0; nt < 8; ++nt) {
                int nb = (wn * 64 + nt * 8 + r4) * S40 + kk + c2;
                uint2 q0 = *reinterpret_cast<const uint2*>(&sB[nb]);
                uint2 q1 = *reinterpret_cast<const uint2*>(&sB[nb + 8]);
                uint32_t bh[2], bl[2];
                bh[0] = __byte_perm(q0.x, q0.y, 0x7632);
                bl[0] = __byte_perm(q0.x, q0.y, 0x5410);
                bh[1] = __byte_perm(q1.x, q1.y, 0x7632);
                bl[1] = __byte_perm(q1.x, q1.y, 0x5410);
#pragma unroll
                for (int mt = 0; mt < 2; ++mt) {
                    mma_bf16(acc[mt][nt], ah[mt], bh);
                    mma_bf16(acc[mt][nt], al[mt], bh);
                    mma_bf16(acc[mt][nt], ah[mt], bl);
                }
            }
        }
        __syncthreads();
        if (c + 2 < NCH) issue(c + 2);
    }

    // ---- epilogue ----
    uint32_t* Cp = (csel == 1) ? g_h0p : g_h1p;
#pragma unroll
    for (int nt = 0; nt < 8; ++nt) {
        int col = bn + wn * 64 + nt * 8 + c2;
        float2 bv = *reinterpret_cast<const float2*>(bias + col);
#pragma unroll
        for (int mt = 0; mt < 2; ++mt) {
            int row0 = bm + wm * 32 + mt * 16 + r4;
            float2 o0, o1;
            o0.x = acc[mt][nt][0] + bv.x;
            o0.y = acc[mt][nt][1] + bv.y;
            o1.x = acc[mt][nt][2] + bv.x;
            o1.y = acc[mt][nt][3] + bv.y;
            if (relu) {
                o0.x = fmaxf(o0.x, 0.f); o0.y = fmaxf(o0.y, 0.f);
                o1.x = fmaxf(o1.x, 0.f); o1.y = fmaxf(o1.y, 0.f);
            }
            if (csel == 0) {
                if (row0 < NN)
                    *reinterpret_cast<float2*>(Cext + (size_t)row0 * 256 + col) = o0;
                if (row0 + 8 < NN)
                    *reinterpret_cast<float2*>(Cext + (size_t)(row0 + 8) * 256 + col) = o1;
            } else {
                if (row0 < NN) {
                    uint2 p = make_uint2(pack_split(o0.x), pack_split(o0.y));
                    *reinterpret_cast<uint2*>(Cp + (size_t)row0 * 256 + col) = p;
                }
                if (row0 + 8 < NN) {
                    uint2 p = make_uint2(pack_split(o1.x), pack_split(o1.y));
                    *reinterpret_cast<uint2*>(Cp + (size_t)(row0 + 8) * 256 + col) = p;
                }
            }
        }
    }
}

// ---------------------------------------------------------------------------
// launch
// ---------------------------------------------------------------------------
extern "C" void kernel_launch(void* const* d_in, const int* in_sizes, int n_in,
                              void* d_out, int out_size) {
    const float* x    = (const float*)d_in[0];
    const float* W_l0 = (const float*)d_in[1];
    const float* b_l0 = (const float*)d_in[2];
    const float* W_r0 = (const float*)d_in[3];
    const float* W_l1 = (const float*)d_in[4];
    const float* b_l1 = (const float*)d_in[5];
    const float* W_r1 = (const float*)d_in[6];
    const float* W_l2 = (const float*)d_in[7];
    const float* b_l2 = (const float*)d_in[8];
    const float* W_r2 = (const float*)d_in[9];
    const int*   src  = (const int*)d_in[10];
    const int*   dst  = (const int*)d_in[11];
    float*       out  = (float*)d_out;

    const int T = 256;
    dim3 gemm_grid((NN + BM - 1) / BM, 256 / BN);

    static bool attr_set = false;
    if (!attr_set) {
        cudaFuncSetAttribute(k_gemm_mma, cudaFuncAttributeMaxDynamicSharedMemorySize,
                             SMEM_BYTES);
        attr_set = true;
    }

    // ---- CSR build ----
    k_zero_cnt<<<(NN + T - 1) / T, T>>>();
    k_hist<<<(NE + T - 1) / T, T>>>(dst);
    k_scan1<<<NB1, SCAN_B>>>();
    k_scan2<<<1, 256>>>();
    k_scan3<<<(NN + T - 1) / T, T>>>();
    k_place<<<(NE + T - 1) / T, T>>>(src, dst);

    // ---- prep: pack x, pack+transpose weights ----
    k_prep_x<<<(NN * 128 + T - 1) / T, T>>>(x);
    k_prep_w<<<(128 * 256 + T - 1) / T, T>>>(W_l0, 128, 0);
    k_prep_w<<<(128 * 256 + T - 1) / T, T>>>(W_r0, 128, 32768);
    k_prep_w<<<(256 * 256 + T - 1) / T, T>>>(W_l1, 256, 65536);
    k_prep_w<<<(256 * 256 + T - 1) / T, T>>>(W_r1, 256, 131072);
    k_prep_w<<<(256 * 256 + T - 1) / T, T>>>(W_l2, 256, 196608);
    k_prep_w<<<(256 * 256 + T - 1) / T, T>>>(W_r2, 256, 262144);

    // ---- layer 0 (K = 128) ----
    k_aggregate<1><<<(NN * 1 * 32 + T - 1) / T, T>>>(0);
    k_gemm_mma<<<gemm_grid, T, SMEM_BYTES>>>(0, 0, 32768, b_l0, nullptr, 1, 128, 1);

    // ---- layer 1 (K = 256) ----
    k_aggregate<2><<<(NN * 2 * 32 + T - 1) / T, T>>>(1);
    k_gemm_mma<<<gemm_grid, T, SMEM_BYTES>>>(1, 65536, 131072, b_l1, nullptr, 2, 256, 1);

    // ---- layer 2 (K = 256, no relu, write d_out) ----
    k_aggregate<2><<<(NN * 2 * 32 + T - 1) / T, T>>>(2);
    k_gemm_mma<<<gemm_grid, T, SMEM_BYTES>>>(2, 196608, 262144, b_l2, out, 0, 256, 0);
}